// round 8
// baseline (speedup 1.0000x reference)
#include <cuda_runtime.h>
#include <math.h>

#define Bn    256
#define Cn    112
#define C2    224
#define Pn    200
#define Dn    10
#define NCLSn 200
#define NPAIR 112
#define NBATCH 256
#define NBCE  112
#define NB    (NPAIR + NBATCH + NBCE)   // 480 blocks
#define NGRP  32                        // 480/32 = 15 blocks per group

// ---------------- device scratch (fully rewritten every launch) -------------
__device__ unsigned long long g_mask[C2][4];
__device__ int   g_gidx[C2][10];
__device__ float g_aop[Cn];
__device__ float g_oc[Cn];
__device__ float g_part_ent[Cn];
__device__ float g_clst[Bn];
__device__ float g_sep[Bn];
__device__ float g_tl[Bn];
__device__ float g_l1[Bn];
__device__ int   g_rdy[NPAIR * 8];      // per-pair ready flag, 32B padded
__device__ int   g_done0[NGRP * 8];     // level-0 done counters, 32B padded
__device__ int   g_done1;               // master

// order-preserving float->uint (monotonic)
__device__ __forceinline__ unsigned f2ord(float f) {
    unsigned u = __float_as_uint(f);
    return (u & 0x80000000u) ? ~u : (u | 0x80000000u);
}

// ---------------------------------------------------------------------------
// warp top-10 LARGEST (ties -> lower index) via REDUX; lane0 writes + fences.
__device__ __forceinline__ void topk10_redux(const float* s, int r) {
    const int lane = threadIdx.x & 31;
    unsigned key[7];
    #pragma unroll
    for (int k = 0; k < 7; k++) {
        int p = lane + 32 * k;
        key[k] = (p < Pn) ? f2ord(s[p]) : 0u;
    }
    unsigned used = 0;
    unsigned long long mask[4] = {0ull, 0ull, 0ull, 0ull};
    #pragma unroll
    for (int it = 0; it < 10; it++) {
        unsigned bk = 0u; unsigned bi = 0xffffffffu;
        #pragma unroll
        for (int k = 0; k < 7; k++) {
            if (!((used >> k) & 1u) && key[k] > bk) { bk = key[k]; bi = lane + 32u * k; }
        }
        unsigned wmax = __reduce_max_sync(0xffffffffu, bk);
        unsigned cand = (bk == wmax) ? bi : 0xffffffffu;
        unsigned widx = __reduce_min_sync(0xffffffffu, cand);
        if ((widx & 31u) == (unsigned)lane) used |= 1u << (widx >> 5);
        if (lane == 0) { mask[widx >> 6] |= 1ull << (widx & 63u); g_gidx[r][it] = (int)widx; }
    }
    if (lane == 0) {
        #pragma unroll
        for (int w = 0; w < 4; w++) g_mask[r][w] = mask[w];
        __threadfence();   // order data stores before the ready flag
    }
}

// warp 11-SMALLEST (ascending; ties -> lower index) into smem lists.
__device__ __forceinline__ void mink11_redux(const float* s, int* ci, float* cv) {
    const int lane = threadIdx.x & 31;
    unsigned key[7];
    #pragma unroll
    for (int k = 0; k < 7; k++) {
        int p = lane + 32 * k;
        key[k] = (p < Pn) ? f2ord(s[p]) : 0xffffffffu;
    }
    unsigned used = 0;
    #pragma unroll
    for (int it = 0; it < 11; it++) {
        unsigned bk = 0xffffffffu; unsigned bi = 0xffffffffu;
        #pragma unroll
        for (int k = 0; k < 7; k++) {
            if (!((used >> k) & 1u) && key[k] < bk) { bk = key[k]; bi = lane + 32u * k; }
        }
        unsigned wmin = __reduce_min_sync(0xffffffffu, bk);
        unsigned cand = (bk == wmin) ? bi : 0xffffffffu;
        unsigned widx = __reduce_min_sync(0xffffffffu, cand);
        if ((widx & 31u) == (unsigned)lane) used |= 1u << (widx >> 5);
        if (lane == 0) { ci[it] = (int)widx; cv[it] = s[widx]; }
    }
}

// block sum over 256 threads (valid at t==0).
__device__ __forceinline__ float bsum256(float v, float* s, int t) {
    __syncthreads();
    #pragma unroll
    for (int off = 16; off; off >>= 1) v += __shfl_down_sync(0xffffffffu, v, off);
    if ((t & 31) == 0) s[t >> 5] = v;
    __syncthreads();
    float r = 0.f;
    if (t == 0) {
        #pragma unroll
        for (int i = 0; i < 8; i++) r += s[i];
    }
    return r;
}

// ---------------------------------------------------------------------------
__global__ __launch_bounds__(256) void fused(const float* __restrict__ proto,
                                             const float* __restrict__ mind,
                                             const float* __restrict__ cy,
                                             const float* __restrict__ tlog,
                                             const int* __restrict__ tt,
                                             const float* __restrict__ wgt,
                                             const float* __restrict__ msk,
                                             const float* __restrict__ cx,
                                             float* __restrict__ out) {
    __shared__ float rA[Pn * Dn];
    __shared__ float rB[Pn * Dn];
    __shared__ float sA[Pn];
    __shared__ float sB[Pn];
    __shared__ float part[Pn];
    __shared__ float invn[2][Dn];
    __shared__ int   candi[11];
    __shared__ float candv[11];
    __shared__ float reds[8], reds2[8];
    __shared__ float fin[8][7];
    __shared__ int   amLast;

    const int bid  = blockIdx.x;
    const int t    = threadIdx.x;
    const int lane = t & 31;
    const int w    = t >> 5;

    if (bid < NPAIR) {
        // =================== pair block: proto rows c, c+C ==================
        const int c = bid;
        const float4* pA = (const float4*)(proto + (size_t)c * Pn * Dn);
        const float4* pB = (const float4*)(proto + (size_t)(c + Cn) * Pn * Dn);
        #pragma unroll
        for (int i = t; i < (Pn * Dn) / 4; i += 256) {
            ((float4*)rA)[i] = pA[i];
            ((float4*)rB)[i] = pB[i];
        }
        __syncthreads();

        if (t < Pn) {
            float a = 0.f, b2 = 0.f;
            #pragma unroll
            for (int d = 0; d < Dn; d++) { a += rA[t * Dn + d]; b2 += rB[t * Dn + d]; }
            sA[t] = a; sB[t] = b2;

            int which = t / 100, rem = t % 100;
            int d = rem / 10, seg = rem % 10;
            const float* r = which ? rB : rA;
            float s = 0.f;
            #pragma unroll
            for (int p = seg * 20; p < seg * 20 + 20; p++) {
                float v = r[p * Dn + d]; s += v * v;
            }
            part[t] = s;
        }
        __syncthreads();
        if (t < 20) {
            int which = t / 10, d = t % 10;
            float s = 0.f;
            #pragma unroll
            for (int seg = 0; seg < 10; seg++) s += part[which * 100 + d * 10 + seg];
            invn[which][d] = rsqrtf(fmaxf(s, 1e-16f));
        }
        __syncthreads();

        // warp0/1: topk + EARLY flag publish (named barrier over 64 threads)
        float aop = 0.f, oc = 0.f;
        if (w == 0) {
            topk10_redux(sA, c);
        } else if (w == 1) {
            topk10_redux(sB, c + Cn);
        } else {
            for (int p = t - 64; p < Pn; p += 192) {
                float ua = 0.f, ub = 0.f;
                #pragma unroll
                for (int d = 0; d < Dn; d++) {
                    ua += rA[p * Dn + d] * invn[0][d];
                    ub += rB[p * Dn + d] * invn[1][d];
                }
                aop += ua * ua + ub * ub;
                oc  += ua * ub;
            }
            #pragma unroll
            for (int off = 16; off; off >>= 1) {
                aop += __shfl_down_sync(0xffffffffu, aop, off);
                oc  += __shfl_down_sync(0xffffffffu, oc, off);
            }
            if (lane == 0) { reds[w] = aop; reds2[w] = oc; }
        }
        if (w < 2) {
            asm volatile("bar.sync 1, 64;" ::: "memory");
            if (t == 0) *((volatile int*)&g_rdy[c * 8]) = 1;   // release flag
        }
        __syncthreads();
        if (t == 0) {
            g_aop[c] = reds[2] + reds[3] + reds[4] + reds[5] + reds[6] + reds[7];
            g_oc[c]  = reds2[2] + reds2[3] + reds2[4] + reds2[5] + reds2[6] + reds2[7];
        }

    } else if (bid < NPAIR + NBATCH) {
        // =================== per-batch block (b) ============================
        const int b = bid - NPAIR;
        if (t < Pn) sA[t] = mind[b * Pn + t];
        if (t < Cn) sB[t] = cy[b * Cn + t];
        __syncthreads();

        if (w == 0) {
            mink11_redux(sA, candi, candv);
        } else if (w == 1) {
            // log-softmax target loss
            float v[7];
            float mx = -1e30f;
            #pragma unroll
            for (int k = 0; k < 7; k++) {
                int p = lane + 32 * k;
                v[k] = (p < NCLSn) ? tlog[b * NCLSn + p] : -1e30f;
                mx = fmaxf(mx, v[k]);
            }
            #pragma unroll
            for (int off = 16; off; off >>= 1)
                mx = fmaxf(mx, __shfl_xor_sync(0xffffffffu, mx, off));
            float se = 0.f;
            #pragma unroll
            for (int k = 0; k < 7; k++) {
                int p = lane + 32 * k;
                if (p < NCLSn) se += expf(v[k] - mx);
            }
            #pragma unroll
            for (int off = 16; off; off >>= 1)
                se += __shfl_xor_sync(0xffffffffu, se, off);
            if (lane == 0) {
                int cls = tt[b];
                g_tl[b] = -(tlog[b * NCLSn + cls] - mx - logf(se));
            }
        } else if (w == 2) {
            // l1 slice [b*175, b*175+175)
            float lp = 0.f;
            int base = b * 175;
            #pragma unroll
            for (int k = 0; k < 6; k++) {
                int i = lane + 32 * k;
                if (i < 175) lp += fabsf(wgt[base + i] * msk[base + i]);
            }
            #pragma unroll
            for (int off = 16; off; off >>= 1)
                lp += __shfl_down_sync(0xffffffffu, lp, off);
            if (lane == 0) g_l1[b] = lp;
        }

        // per-thread acquire spin on the one flag this thread needs
        float m1s = 0.f, m2s = 0.f;
        if (t < Cn) {
            while (*((volatile int*)&g_rdy[t * 8]) == 0) __nanosleep(20);
        }
        __threadfence();   // acquire: order flag read before data reads
        __syncthreads();

        if (t < Cn) {
            const int c = t;
            float yv = sB[c];
            bool pos = (yv > 0.5f);
            int r1 = pos ? c : c + Cn;
            int r2 = pos ? c + Cn : c;
            const int* gi = g_gidx[r1];
            float m1 = 1e30f;
            #pragma unroll
            for (int k = 0; k < 10; k++) m1 = fminf(m1, sA[gi[k]]);
            unsigned long long w0 = g_mask[r2][0], w1 = g_mask[r2][1];
            unsigned long long w2 = g_mask[r2][2], w3 = g_mask[r2][3];
            float m2 = 1e30f;
            #pragma unroll
            for (int k = 0; k < 11; k++) {
                int id = candi[k];
                unsigned long long wsel = (id < 64) ? w0 : (id < 128) ? w1
                                        : (id < 192) ? w2 : w3;
                if (!((wsel >> (id & 63)) & 1ull)) { m2 = candv[k]; break; }
            }
            m1s = m1; m2s = m2;
        }
        float s1 = bsum256(m1s, reds, t);
        float s2 = bsum256(m2s, reds, t);
        if (t == 0) { g_clst[b] = s1; g_sep[b] = s2; }

    } else {
        // =================== per-concept BCE block (no waits) ===============
        const int c = bid - NPAIR - NBATCH;
        float x = cx[t * Cn + c], y = cy[t * Cn + c];
        float bce = fmaxf(x, 0.f) + log1pf(expf(-fabsf(x))) - x * y;
        float bs = bsum256(bce, reds, t);
        if (t == 0) {
            out[1 + c] = bs / (float)Bn;
            g_part_ent[c] = bs;
        }
    }

    // =================== hierarchical done + finale =========================
    __threadfence();
    if (t == 0) {
        int last = 0;
        int r0 = atomicAdd(&g_done0[(bid & (NGRP - 1)) * 8], 1);
        if (r0 == (NB / NGRP) - 1) {
            int r1 = atomicAdd(&g_done1, 1);
            last = (r1 == NGRP - 1);
        }
        amLast = last;
    }
    __syncthreads();
    if (amLast) {
        float a0 = g_l1[t],   a1 = g_tl[t], a2 = g_clst[t], a3 = g_sep[t];
        float a4 = (t < Cn) ? g_part_ent[t] : 0.f;
        float a5 = (t < Cn) ? g_aop[t] : 0.f;
        float a6 = (t < Cn) ? g_oc[t]  : 0.f;
        #pragma unroll
        for (int off = 16; off; off >>= 1) {
            a0 += __shfl_down_sync(0xffffffffu, a0, off);
            a1 += __shfl_down_sync(0xffffffffu, a1, off);
            a2 += __shfl_down_sync(0xffffffffu, a2, off);
            a3 += __shfl_down_sync(0xffffffffu, a3, off);
            a4 += __shfl_down_sync(0xffffffffu, a4, off);
            a5 += __shfl_down_sync(0xffffffffu, a5, off);
            a6 += __shfl_down_sync(0xffffffffu, a6, off);
        }
        if (lane == 0) {
            fin[w][0] = a0; fin[w][1] = a1; fin[w][2] = a2; fin[w][3] = a3;
            fin[w][4] = a4; fin[w][5] = a5; fin[w][6] = a6;
        }
        __syncthreads();
        if (t == 0) {
            float s[7];
            #pragma unroll
            for (int j = 0; j < 7; j++) {
                float acc = 0.f;
                #pragma unroll
                for (int i = 0; i < 8; i++) acc += fin[i][j];
                s[j] = acc;
            }
            float target_loss = s[1] / (float)Bn;
            float entropy     = s[4] / (float)(Bn * Cn);
            float clst        = s[2] / (float)(Bn * Cn);
            float sep         = s[3] / (float)(Bn * Cn);
            float ortho_p     = s[5] / (float)(Dn * Cn * 2) - 1.0f;
            float ortho_c     = s[6] / (float)(Dn * Cn);
            float l1          = s[0];
            float summed = entropy + 0.8f * clst + (-0.08f) * sep
                         + 1e-4f * l1 + ortho_p + ortho_c;
            out[0]   = target_loss;
            out[113] = summed;
            out[114] = target_loss + summed;
            out[115] = entropy;
            out[116] = clst;
            out[117] = sep;
            out[118] = l1;
            out[119] = ortho_p;
            out[120] = ortho_c;
        }
        // reset all flags/counters for next graph replay (we are provably last)
        if (t < NPAIR) g_rdy[t * 8] = 0;
        if (t < NGRP)  g_done0[t * 8] = 0;
        if (t == 0)    g_done1 = 0;
    }
}

// ---------------------------------------------------------------------------
extern "C" void kernel_launch(void* const* d_in, const int* in_sizes, int n_in,
                              void* d_out, int out_size) {
    const float* cx    = (const float*)d_in[0];
    const float* cy    = (const float*)d_in[1];
    const float* mind  = (const float*)d_in[2];
    const float* proto = (const float*)d_in[3];
    const float* tlog  = (const float*)d_in[4];
    const int*   tt    = (const int*)d_in[5];
    const float* wgt   = (const float*)d_in[6];
    const float* msk   = (const float*)d_in[7];
    float* out = (float*)d_out;

    fused<<<NB, 256>>>(proto, mind, cy, tlog, tt, wgt, msk, cx, out);
}

// round 9
// speedup vs baseline: 1.1675x; 1.1675x over previous
#include <cuda_runtime.h>
#include <math.h>

#define Bn    256
#define Cn    112
#define C2    224
#define Pn    200
#define Dn    10
#define NCLSn 200
#define NPAIR 112
#define NBATCH 256
#define NBCE  112
#define NB    (NPAIR + NBATCH + NBCE)   // 480 blocks

// ---------------- device scratch (fully rewritten every launch) -------------
__device__ unsigned long long g_mask[C2][4];
__device__ int   g_gidx[C2][10];
__device__ float g_aop[Cn];
__device__ float g_oc[Cn];
__device__ float g_part_ent[Cn];
__device__ float g_clst[Bn];
__device__ float g_sep[Bn];
__device__ float g_tl[Bn];
__device__ float g_l1[Bn];
__device__ int   g_bar;    // pair publications (target NPAIR)
__device__ int   g_done;

// order-preserving float->uint (monotonic)
__device__ __forceinline__ unsigned f2ord(float f) {
    unsigned u = __float_as_uint(f);
    return (u & 0x80000000u) ? ~u : (u | 0x80000000u);
}

// ---------------------------------------------------------------------------
// warp top-10 LARGEST (ties -> lower index) via REDUX; lane0 writes + fence.
__device__ __forceinline__ void topk10_redux(const float* s, int r) {
    const int lane = threadIdx.x & 31;
    unsigned key[7];
    #pragma unroll
    for (int k = 0; k < 7; k++) {
        int p = lane + 32 * k;
        key[k] = (p < Pn) ? f2ord(s[p]) : 0u;
    }
    unsigned used = 0;
    unsigned long long mask[4] = {0ull, 0ull, 0ull, 0ull};
    #pragma unroll
    for (int it = 0; it < 10; it++) {
        unsigned bk = 0u; unsigned bi = 0xffffffffu;
        #pragma unroll
        for (int k = 0; k < 7; k++) {
            if (!((used >> k) & 1u) && key[k] > bk) { bk = key[k]; bi = lane + 32u * k; }
        }
        unsigned wmax = __reduce_max_sync(0xffffffffu, bk);
        unsigned cand = (bk == wmax) ? bi : 0xffffffffu;
        unsigned widx = __reduce_min_sync(0xffffffffu, cand);
        if ((widx & 31u) == (unsigned)lane) used |= 1u << (widx >> 5);
        if (lane == 0) { mask[widx >> 6] |= 1ull << (widx & 63u); g_gidx[r][it] = (int)widx; }
    }
    if (lane == 0) {
        #pragma unroll
        for (int w = 0; w < 4; w++) g_mask[r][w] = mask[w];
        __threadfence();   // release: data before counter bump
    }
}

// warp 11-SMALLEST (ascending; ties -> lower index) into smem lists.
__device__ __forceinline__ void mink11_redux(const float* s, int* ci, float* cv) {
    const int lane = threadIdx.x & 31;
    unsigned key[7];
    #pragma unroll
    for (int k = 0; k < 7; k++) {
        int p = lane + 32 * k;
        key[k] = (p < Pn) ? f2ord(s[p]) : 0xffffffffu;
    }
    unsigned used = 0;
    #pragma unroll
    for (int it = 0; it < 11; it++) {
        unsigned bk = 0xffffffffu; unsigned bi = 0xffffffffu;
        #pragma unroll
        for (int k = 0; k < 7; k++) {
            if (!((used >> k) & 1u) && key[k] < bk) { bk = key[k]; bi = lane + 32u * k; }
        }
        unsigned wmin = __reduce_min_sync(0xffffffffu, bk);
        unsigned cand = (bk == wmin) ? bi : 0xffffffffu;
        unsigned widx = __reduce_min_sync(0xffffffffu, cand);
        if ((widx & 31u) == (unsigned)lane) used |= 1u << (widx >> 5);
        if (lane == 0) { ci[it] = (int)widx; cv[it] = s[widx]; }
    }
}

// block sum over 256 threads (valid at t==0).
__device__ __forceinline__ float bsum256(float v, float* s, int t) {
    __syncthreads();
    #pragma unroll
    for (int off = 16; off; off >>= 1) v += __shfl_down_sync(0xffffffffu, v, off);
    if ((t & 31) == 0) s[t >> 5] = v;
    __syncthreads();
    float r = 0.f;
    if (t == 0) {
        #pragma unroll
        for (int i = 0; i < 8; i++) r += s[i];
    }
    return r;
}

// ---------------------------------------------------------------------------
__global__ __launch_bounds__(256) void fused(const float* __restrict__ proto,
                                             const float* __restrict__ mind,
                                             const float* __restrict__ cy,
                                             const float* __restrict__ tlog,
                                             const int* __restrict__ tt,
                                             const float* __restrict__ wgt,
                                             const float* __restrict__ msk,
                                             const float* __restrict__ cx,
                                             float* __restrict__ out) {
    __shared__ float rA[Pn * Dn];
    __shared__ float rB[Pn * Dn];
    __shared__ float sA[Pn];
    __shared__ float sB[Pn];
    __shared__ float part[Pn];
    __shared__ float invn[2][Dn];
    __shared__ int   candi[11];
    __shared__ float candv[11];
    __shared__ float reds[8];
    __shared__ float fin[8][7];
    __shared__ int   amLast;

    const int bid  = blockIdx.x;
    const int t    = threadIdx.x;
    const int lane = t & 31;
    const int w    = t >> 5;

    if (bid < NPAIR) {
        // =================== pair block: proto rows c, c+C ==================
        const int c = bid;

        // phase 0: row sums straight from global (critical path for topk)
        if (t < Pn) {
            const float2* ra = (const float2*)(proto + ((size_t)c * Pn + t) * Dn);
            const float2* rb = (const float2*)(proto + ((size_t)(c + Cn) * Pn + t) * Dn);
            float a = 0.f, b2 = 0.f;
            #pragma unroll
            for (int k = 0; k < 5; k++) {
                float2 va = ra[k]; a += va.x + va.y;
                float2 vb = rb[k]; b2 += vb.x + vb.y;
            }
            sA[t] = a; sB[t] = b2;
        }
        __syncthreads();

        // warps 0/1: topk + EARLY publish; warps 2-7: stage tile into smem
        if (w == 0) {
            topk10_redux(sA, c);
        } else if (w == 1) {
            topk10_redux(sB, c + Cn);
        } else {
            const float4* pA = (const float4*)(proto + (size_t)c * Pn * Dn);
            const float4* pB = (const float4*)(proto + (size_t)(c + Cn) * Pn * Dn);
            for (int i = t - 64; i < (Pn * Dn) / 4; i += 192) {
                ((float4*)rA)[i] = pA[i];
                ((float4*)rB)[i] = pB[i];
            }
        }
        if (w < 2) {
            asm volatile("bar.sync 1, 64;" ::: "memory");
            if (t == 0) atomicAdd(&g_bar, 1);    // one release per pair
        }
        __syncthreads();

        // norms
        if (t < Pn) {
            int which = t / 100, rem = t % 100;
            int d = rem / 10, seg = rem % 10;
            const float* r = which ? rB : rA;
            float s = 0.f;
            #pragma unroll
            for (int p = seg * 20; p < seg * 20 + 20; p++) {
                float v = r[p * Dn + d]; s += v * v;
            }
            part[t] = s;
        }
        __syncthreads();
        if (t < 20) {
            int which = t / 10, d = t % 10;
            float s = 0.f;
            #pragma unroll
            for (int seg = 0; seg < 10; seg++) s += part[which * 100 + d * 10 + seg];
            invn[which][d] = rsqrtf(fmaxf(s, 1e-16f));
        }
        __syncthreads();

        // ortho partials (one row per thread)
        float aop = 0.f, oc = 0.f;
        if (t < Pn) {
            float ua = 0.f, ub = 0.f;
            #pragma unroll
            for (int d = 0; d < Dn; d++) {
                ua += rA[t * Dn + d] * invn[0][d];
                ub += rB[t * Dn + d] * invn[1][d];
            }
            aop = ua * ua + ub * ub;
            oc  = ua * ub;
        }
        float sa = bsum256(aop, reds, t);
        float so = bsum256(oc, reds, t);
        if (t == 0) { g_aop[c] = sa; g_oc[c] = so; }

    } else if (bid < NPAIR + NBATCH) {
        // =================== per-batch block (b) ============================
        const int b = bid - NPAIR;
        if (t < Pn) sA[t] = mind[b * Pn + t];
        if (t < Cn) sB[t] = cy[b * Cn + t];
        __syncthreads();

        if (w == 0) {
            mink11_redux(sA, candi, candv);
        } else if (w == 1) {
            // log-softmax target loss
            float v[7];
            float mx = -1e30f;
            #pragma unroll
            for (int k = 0; k < 7; k++) {
                int p = lane + 32 * k;
                v[k] = (p < NCLSn) ? tlog[b * NCLSn + p] : -1e30f;
                mx = fmaxf(mx, v[k]);
            }
            #pragma unroll
            for (int off = 16; off; off >>= 1)
                mx = fmaxf(mx, __shfl_xor_sync(0xffffffffu, mx, off));
            float se = 0.f;
            #pragma unroll
            for (int k = 0; k < 7; k++) {
                int p = lane + 32 * k;
                if (p < NCLSn) se += expf(v[k] - mx);
            }
            #pragma unroll
            for (int off = 16; off; off >>= 1)
                se += __shfl_xor_sync(0xffffffffu, se, off);
            if (lane == 0) {
                int cls = tt[b];
                g_tl[b] = -(tlog[b * NCLSn + cls] - mx - logf(se));
            }
        } else if (w == 2) {
            // l1 slice [b*175, b*175+175)
            float lp = 0.f;
            int base = b * 175;
            #pragma unroll
            for (int k = 0; k < 6; k++) {
                int i = lane + 32 * k;
                if (i < 175) lp += fabsf(wgt[base + i] * msk[base + i]);
            }
            #pragma unroll
            for (int off = 16; off; off >>= 1)
                lp += __shfl_down_sync(0xffffffffu, lp, off);
            if (lane == 0) g_l1[b] = lp;
        }

        // wait for all pair publications (single cached counter, one spinner)
        if (t == 0) {
            while (*((volatile int*)&g_bar) < NPAIR) __nanosleep(20);
        }
        __syncthreads();
        __threadfence();

        float m1s = 0.f, m2s = 0.f;
        if (t < Cn) {
            const int c = t;
            float yv = sB[c];
            bool pos = (yv > 0.5f);
            int r1 = pos ? c : c + Cn;
            int r2 = pos ? c + Cn : c;
            const int* gi = g_gidx[r1];
            float m1 = 1e30f;
            #pragma unroll
            for (int k = 0; k < 10; k++) m1 = fminf(m1, sA[gi[k]]);
            unsigned long long w0 = g_mask[r2][0], w1 = g_mask[r2][1];
            unsigned long long w2 = g_mask[r2][2], w3 = g_mask[r2][3];
            float m2 = 1e30f;
            #pragma unroll
            for (int k = 0; k < 11; k++) {
                int id = candi[k];
                unsigned long long wsel = (id < 64) ? w0 : (id < 128) ? w1
                                        : (id < 192) ? w2 : w3;
                if (!((wsel >> (id & 63)) & 1ull)) { m2 = candv[k]; break; }
            }
            m1s = m1; m2s = m2;
        }
        float s1 = bsum256(m1s, reds, t);
        float s2 = bsum256(m2s, reds, t);
        if (t == 0) { g_clst[b] = s1; g_sep[b] = s2; }

    } else {
        // =================== per-concept BCE block (no waits) ===============
        const int c = bid - NPAIR - NBATCH;
        float x = cx[t * Cn + c], y = cy[t * Cn + c];
        float bce = fmaxf(x, 0.f) + log1pf(expf(-fabsf(x))) - x * y;
        float bs = bsum256(bce, reds, t);
        if (t == 0) {
            out[1 + c] = bs / (float)Bn;
            g_part_ent[c] = bs;
        }
    }

    // =================== last-block finale ==================================
    __threadfence();
    if (t == 0) amLast = (atomicAdd(&g_done, 1) == NB - 1);
    __syncthreads();
    if (amLast) {
        float a0 = g_l1[t],   a1 = g_tl[t], a2 = g_clst[t], a3 = g_sep[t];
        float a4 = (t < Cn) ? g_part_ent[t] : 0.f;
        float a5 = (t < Cn) ? g_aop[t] : 0.f;
        float a6 = (t < Cn) ? g_oc[t]  : 0.f;
        #pragma unroll
        for (int off = 16; off; off >>= 1) {
            a0 += __shfl_down_sync(0xffffffffu, a0, off);
            a1 += __shfl_down_sync(0xffffffffu, a1, off);
            a2 += __shfl_down_sync(0xffffffffu, a2, off);
            a3 += __shfl_down_sync(0xffffffffu, a3, off);
            a4 += __shfl_down_sync(0xffffffffu, a4, off);
            a5 += __shfl_down_sync(0xffffffffu, a5, off);
            a6 += __shfl_down_sync(0xffffffffu, a6, off);
        }
        if (lane == 0) {
            fin[w][0] = a0; fin[w][1] = a1; fin[w][2] = a2; fin[w][3] = a3;
            fin[w][4] = a4; fin[w][5] = a5; fin[w][6] = a6;
        }
        __syncthreads();
        if (t == 0) {
            float s[7];
            #pragma unroll
            for (int j = 0; j < 7; j++) {
                float acc = 0.f;
                #pragma unroll
                for (int i = 0; i < 8; i++) acc += fin[i][j];
                s[j] = acc;
            }
            float target_loss = s[1] / (float)Bn;
            float entropy     = s[4] / (float)(Bn * Cn);
            float clst        = s[2] / (float)(Bn * Cn);
            float sep         = s[3] / (float)(Bn * Cn);
            float ortho_p     = s[5] / (float)(Dn * Cn * 2) - 1.0f;
            float ortho_c     = s[6] / (float)(Dn * Cn);
            float l1          = s[0];
            float summed = entropy + 0.8f * clst + (-0.08f) * sep
                         + 1e-4f * l1 + ortho_p + ortho_c;
            out[0]   = target_loss;
            out[113] = summed;
            out[114] = target_loss + summed;
            out[115] = entropy;
            out[116] = clst;
            out[117] = sep;
            out[118] = l1;
            out[119] = ortho_p;
            out[120] = ortho_c;
            g_bar  = 0;          // reset for next graph replay (provably last)
            g_done = 0;
        }
    }
}

// ---------------------------------------------------------------------------
extern "C" void kernel_launch(void* const* d_in, const int* in_sizes, int n_in,
                              void* d_out, int out_size) {
    const float* cx    = (const float*)d_in[0];
    const float* cy    = (const float*)d_in[1];
    const float* mind  = (const float*)d_in[2];
    const float* proto = (const float*)d_in[3];
    const float* tlog  = (const float*)d_in[4];
    const int*   tt    = (const int*)d_in[5];
    const float* wgt   = (const float*)d_in[6];
    const float* msk   = (const float*)d_in[7];
    float* out = (float*)d_out;

    fused<<<NB, 256>>>(proto, mind, cy, tlog, tt, wgt, msk, cx, out);
}